// round 13
// baseline (speedup 1.0000x reference)
#include <cuda_runtime.h>
#include <cuda.h>
#include <cstdint>

#define BB 8
#define NN 256
#define DD 64

// smem byte offsets (dynamic smem base)
#define OFF_MBAR 65536
#define OFF_ASH  65664
#define OFF_RED  66688
#define SMEM_SZ  68736

__device__ float g_node_x[BB * NN * DD];   // emb_node @ Wn + bn
__device__ float g_sx_relu[BB * NN * DD];  // relu(emb_node @ Wsn + bsn)
__device__ float4 g_Wpack[1024];           // We fragments, tf32(rna), b-frag order

// ---------------------------------------------------------------------------
// helpers
// ---------------------------------------------------------------------------
__device__ __forceinline__ float cvt_tf32(float x) {
    float r;
    asm("cvt.rna.tf32.f32 %0, %1;" : "=f"(r) : "f"(x));
    return r;
}
__device__ __forceinline__ uint32_t fbits(float x) { return __float_as_uint(x); }

__device__ __forceinline__ void mma_tf32(float* c, const uint32_t* a,
                                         uint32_t b0, uint32_t b1) {
    asm volatile(
        "mma.sync.aligned.m16n8k8.row.col.f32.tf32.tf32.f32 "
        "{%0,%1,%2,%3}, {%4,%5,%6,%7}, {%8,%9}, {%0,%1,%2,%3};"
        : "+f"(c[0]), "+f"(c[1]), "+f"(c[2]), "+f"(c[3])
        : "r"(a[0]), "r"(a[1]), "r"(a[2]), "r"(a[3]), "r"(b0), "r"(b1));
}

__device__ __forceinline__ void cp_async16(uint32_t saddr, const void* gptr) {
    asm volatile("cp.async.cg.shared.global [%0], [%1], 16;"
                 :: "r"(saddr), "l"(gptr));
}

__device__ __forceinline__ uint32_t smem_u32(const void* p) {
    uint32_t a;
    asm("{ .reg .u64 t; cvta.to.shared.u64 t, %1; cvt.u32.u64 %0, t; }"
        : "=r"(a) : "l"(p));
    return a;
}

#define MBARRIER_INIT(mbar, cnt) \
    asm volatile("mbarrier.init.shared.b64 [%0], %1;" \
                 :: "r"((uint32_t)(mbar)), "r"((uint32_t)(cnt)) : "memory")
#define MBARRIER_EXPECT_TX(mbar, tx) \
    asm volatile("mbarrier.arrive.expect_tx.shared.b64 _, [%0], %1;" \
                 :: "r"((uint32_t)(mbar)), "r"((uint32_t)(tx)) : "memory")
#define MBARRIER_WAIT_PARITY(mbar, parity) do { \
    uint32_t _m = (uint32_t)(mbar), _p = (uint32_t)(parity), _d; \
    asm volatile("{\n\t.reg .pred p;\n\t" \
        "mbarrier.try_wait.parity.acquire.cta.shared::cta.b64 p, [%1], %2;\n\t" \
        "selp.b32 %0, 1, 0, p;\n\t}" : "=r"(_d) : "r"(_m), "r"(_p) : "memory"); \
    if (!_d) { \
        asm volatile("{\n\t.reg .pred P1;\n\tWL_%=:\n\t" \
            "mbarrier.try_wait.parity.acquire.cta.shared::cta.b64 P1, [%0], %1, 0x989680;\n\t" \
            "@P1 bra.uni WD_%=;\n\tbra.uni WL_%=;\n\tWD_%=:\n\t}" \
            :: "r"(_m), "r"(_p) : "memory"); \
    } \
} while (0)

__device__ __forceinline__ void tma_load_2d(uint32_t dst, const CUtensorMap* map,
                                            int x, int y, uint32_t mbar) {
    asm volatile(
        "cp.async.bulk.tensor.2d.shared::cta.global.tile.mbarrier::complete_tx::bytes "
        "[%0], [%1, {%2, %3}], [%4];"
        :: "r"(dst), "l"(map), "r"(x), "r"(y), "r"(mbar) : "memory");
}

// ---------------------------------------------------------------------------
// Kernel A: node GEMMs (4 rows / 256-thread block) + W fragment packing.
// ---------------------------------------------------------------------------
__global__ __launch_bounds__(256)
void node_gemm_kernel(const float* __restrict__ emb_node,
                      const float* __restrict__ Wn,
                      const float* __restrict__ bn,
                      const float* __restrict__ Wsn,
                      const float* __restrict__ bsn,
                      const float* __restrict__ We) {
    if (blockIdx.x == 0) {
#pragma unroll
        for (int it = 0; it < 4; it++) {
            const int e = threadIdx.x + it * 256;   // 0..1023
            const int p = e >> 8;
            const int nt = (e >> 5) & 7;
            const int l = e & 31;
            const int n = nt * 8 + (l >> 2);
            const int k0 = p * 16 + (l & 3);
            g_Wpack[e] = make_float4(cvt_tf32(We[k0 * DD + n]),
                                     cvt_tf32(We[(k0 + 4) * DD + n]),
                                     cvt_tf32(We[(k0 + 8) * DD + n]),
                                     cvt_tf32(We[(k0 + 12) * DD + n]));
        }
    }
    const int sub = threadIdx.x >> 6;
    const int c = threadIdx.x & 63;
    const int r = blockIdx.x * 4 + sub;
    __shared__ float e[4][DD];
    e[sub][c] = emb_node[r * DD + c];
    __syncthreads();
    float a1 = bn[c];
    float a2 = bsn[c];
#pragma unroll
    for (int k = 0; k < DD; k++) {
        const float ev = e[sub][k];
        a1 = fmaf(ev, Wn[k * DD + c], a1);
        a2 = fmaf(ev, Wsn[k * DD + c], a2);
    }
    g_node_x[r * DD + c] = a1;
    g_sx_relu[r * DD + c] = fmaxf(a2, 0.0f);
}

// ---------------------------------------------------------------------------
// Kernel B: per (b,i). edge_x[256x64] = E @ We via tf32 mma.sync.
// E tile lives in two SW128-swizzled 128B-wide panels (256 rows each):
//   float idx = panel*8192 + row*32 + (kk ^ 4*(row&7)),  kk = col within panel.
// Staged by TMA (use_tma=1) or per-warp cp.async writing the SAME layout.
// a-frag LDS and epilogue readback are bank-conflict-free by construction.
// Epilogue scatters raw acc back into the warp's OWN (dead) panel rows.
// ---------------------------------------------------------------------------
__global__ __launch_bounds__(256, 2)
void edge_mma_kernel(const float* __restrict__ A,
                     const float* __restrict__ emb_edge,
                     const float* __restrict__ be,
                     float* __restrict__ out,
                     const __grid_constant__ CUtensorMap tmap,
                     const int use_tma) {
    const int i = blockIdx.x;
    const int b = blockIdx.y;
    const int tid = threadIdx.x;
    const int lane = tid & 31;
    const int warp = tid >> 5;
    const int g = lane >> 2;     // 0..7
    const int t = lane & 3;      // 0..3
    const int jb = warp * 32;
    const int bi = b * NN + i;

    extern __shared__ float sh[];
    const uint32_t sb = smem_u32(sh);
    float* Esh = sh;                          // 2 panels x 8192 floats
    float* Ash = sh + OFF_ASH / 4;            // 256 floats
    float* red = sh + OFF_RED / 4;            // 8*64 floats

    // ---- stage E tile ----
    if (use_tma) {
        if (tid == 0) MBARRIER_INIT(sb + OFF_MBAR, 1);
        __syncthreads();
        if (tid == 0) {
            MBARRIER_EXPECT_TX(sb + OFF_MBAR, 65536);
            tma_load_2d(sb,         &tmap, 0,  bi * NN, sb + OFF_MBAR);
            tma_load_2d(sb + 32768, &tmap, 32, bi * NN, sb + OFF_MBAR);
        }
    } else {
        const float* Eg = emb_edge + (size_t)bi * NN * DD;
#pragma unroll
        for (int it = 0; it < 16; it++) {
            const int row = jb + it * 2 + (lane >> 4);
            const int c = lane & 15;
            const uint32_t dstB = ((uint32_t)(c >> 3) << 15) + (uint32_t)row * 128u
                                + ((uint32_t)((c & 7) ^ (row & 7)) << 4);
            cp_async16(sb + dstB, Eg + row * DD + c * 4);
        }
        asm volatile("cp.async.commit_group;");
    }
    Ash[jb + lane] = A[(size_t)bi * NN + jb + lane];

    // ---- accumulators init with bias (while loads are in flight) ----
    float acc[2][8][4];
#pragma unroll
    for (int nt = 0; nt < 8; nt++) {
        const float b0 = __ldg(&be[nt * 8 + 2 * t]);
        const float b1 = __ldg(&be[nt * 8 + 2 * t + 1]);
#pragma unroll
        for (int mt = 0; mt < 2; mt++) {
            acc[mt][nt][0] = b0; acc[mt][nt][1] = b1;
            acc[mt][nt][2] = b0; acc[mt][nt][3] = b1;
        }
    }

    if (use_tma) {
        MBARRIER_WAIT_PARITY(sb + OFF_MBAR, 0);
    } else {
        asm volatile("cp.async.wait_group 0;");
        __syncwarp();
    }

    // ---- main loop: 4 k-step pairs ----
    const int xg = g << 2;   // swizzle term: 4*(row&7), row&7 == g for all our rows
#pragma unroll
    for (int p = 0; p < 4; p++) {
        const int panel = (p >> 1) << 13;
        const int kbase = (p & 1) * 16;
        uint32_t a[2][2][4];   // [kb2][mt][reg]
#pragma unroll
        for (int kb2 = 0; kb2 < 2; kb2++) {
#pragma unroll
            for (int mt = 0; mt < 2; mt++) {
                const int row = jb + mt * 16 + g;
                const int k0 = kbase + kb2 * 8 + t;
                const int i0 = panel + row * 32 + (k0 ^ xg);
                const int i2 = panel + row * 32 + ((k0 + 4) ^ xg);
                a[kb2][mt][0] = fbits(cvt_tf32(Esh[i0]));
                a[kb2][mt][1] = fbits(cvt_tf32(Esh[i0 + 256]));   // row+8
                a[kb2][mt][2] = fbits(cvt_tf32(Esh[i2]));
                a[kb2][mt][3] = fbits(cvt_tf32(Esh[i2 + 256]));
            }
        }
        const float4* wrow = &g_Wpack[p * 256 + lane];
#pragma unroll
        for (int nt = 0; nt < 8; nt++) {
            const float4 w = __ldg(&wrow[nt * 32]);
            const uint32_t b0 = fbits(w.x), b1 = fbits(w.y);
            const uint32_t b2 = fbits(w.z), b3 = fbits(w.w);
            mma_tf32(acc[0][nt], a[0][0], b0, b1);
            mma_tf32(acc[1][nt], a[0][1], b0, b1);
            mma_tf32(acc[0][nt], a[1][0], b2, b3);
            mma_tf32(acc[1][nt], a[1][1], b2, b3);
        }
    }

    // ---- epilogue stage 1: scatter raw acc into THIS WARP's panel rows ----
#pragma unroll
    for (int mt = 0; mt < 2; mt++) {
#pragma unroll
        for (int rh = 0; rh < 2; rh++) {
            const int row = jb + mt * 16 + rh * 8 + g;     // row&7 == g
            const int rbase = row * 32;
#pragma unroll
            for (int nt = 0; nt < 8; nt++) {
                const int idx = ((nt >> 2) << 13) + rbase
                              + ((((nt & 3) << 3) + 2 * t) ^ xg);
                *(float2*)&Esh[idx] =
                    make_float2(acc[mt][nt][rh * 2], acc[mt][nt][rh * 2 + 1]);
            }
        }
    }
    __syncwarp();

    // ---- epilogue stage 2: coalesced read-back, relu->edge_out, aggregation ----
    const float* nx = g_node_x + (size_t)b * NN * DD;
    float* eo = out + BB * NN * DD + (size_t)bi * NN * DD;
    const int lr = lane >> 4;
    const int c16 = lane & 15;
    const int panelR = (c16 >> 3) << 13;
    const int colg = (c16 & 7) << 2;
    const int lc = c16 * 4;

    float p0 = 0.0f, p1 = 0.0f, p2 = 0.0f, p3 = 0.0f;
#pragma unroll
    for (int q = 0; q < 16; q++) {
        const int row = jb + 2 * q + lr;
        const int idx = panelR + row * 32 + (colg ^ ((row & 7) << 2));
        const float4 v = *(const float4*)&Esh[idx];
        const float av = Ash[row];
        const float4 nv = *(const float4*)&nx[row * DD + lc];
        *(float4*)&eo[row * DD + lc] =
            make_float4(fmaxf(v.x, 0.0f), fmaxf(v.y, 0.0f),
                        fmaxf(v.z, 0.0f), fmaxf(v.w, 0.0f));
        p0 = fmaf(av * v.x, nv.x, p0);
        p1 = fmaf(av * v.y, nv.y, p1);
        p2 = fmaf(av * v.z, nv.z, p2);
        p3 = fmaf(av * v.w, nv.w, p3);
    }
    p0 += __shfl_xor_sync(0xffffffffu, p0, 16);
    p1 += __shfl_xor_sync(0xffffffffu, p1, 16);
    p2 += __shfl_xor_sync(0xffffffffu, p2, 16);
    p3 += __shfl_xor_sync(0xffffffffu, p3, 16);
    if (lane < 16)
        *(float4*)&red[warp * DD + lc] = make_float4(p0, p1, p2, p3);
    __syncthreads();

    if (tid < DD) {
        float s = 0.0f;
#pragma unroll
        for (int w = 0; w < 8; w++) s += red[w * DD + tid];
        out[(size_t)bi * DD + tid] = fmaxf(s, 0.0f) + g_sx_relu[(size_t)bi * DD + tid];
    }
}

// ---------------------------------------------------------------------------
// Launch
// ---------------------------------------------------------------------------
typedef CUresult (*TmapEncodeFn)(CUtensorMap*, CUtensorMapDataType, cuuint32_t,
                                 void*, const cuuint64_t*, const cuuint64_t*,
                                 const cuuint32_t*, const cuuint32_t*,
                                 CUtensorMapInterleave, CUtensorMapSwizzle,
                                 CUtensorMapL2promotion, CUtensorMapFloatOOBfill);

extern "C" void kernel_launch(void* const* d_in, const int* in_sizes, int n_in,
                              void* d_out, int out_size) {
    const float* A        = (const float*)d_in[0];
    const float* emb_node = (const float*)d_in[1];
    const float* emb_edge = (const float*)d_in[2];
    const float* Wn       = (const float*)d_in[3];
    const float* bn       = (const float*)d_in[4];
    const float* Wsn      = (const float*)d_in[5];
    const float* bsn      = (const float*)d_in[6];
    const float* We       = (const float*)d_in[7];
    const float* be       = (const float*)d_in[8];
    float* out = (float*)d_out;

    // Build the TMA descriptor host-side (capture-time only; replay cost = 0).
    CUtensorMap tmap;
    memset(&tmap, 0, sizeof(tmap));
    int use_tma = 0;
    {
        void* fn = nullptr;
        cudaDriverEntryPointQueryResult qr;
        if (cudaGetDriverEntryPointByVersion("cuTensorMapEncodeTiled", &fn, 12000,
                                             cudaEnableDefault, &qr) == cudaSuccess
            && fn != nullptr) {
            cuuint64_t dims[2]    = {64, (cuuint64_t)BB * NN * NN};
            cuuint64_t strides[1] = {256};          // bytes between rows
            cuuint32_t box[2]     = {32, 256};      // 128B x 256 rows per panel
            cuuint32_t es[2]      = {1, 1};
            if (((TmapEncodeFn)fn)(&tmap, CU_TENSOR_MAP_DATA_TYPE_FLOAT32, 2,
                                   (void*)emb_edge, dims, strides, box, es,
                                   CU_TENSOR_MAP_INTERLEAVE_NONE,
                                   CU_TENSOR_MAP_SWIZZLE_128B,
                                   CU_TENSOR_MAP_L2_PROMOTION_L2_128B,
                                   CU_TENSOR_MAP_FLOAT_OOB_FILL_NONE) == CUDA_SUCCESS)
                use_tma = 1;
        }
    }

    cudaFuncSetAttribute(edge_mma_kernel,
                         cudaFuncAttributeMaxDynamicSharedMemorySize, SMEM_SZ);

    node_gemm_kernel<<<BB * NN / 4, 256>>>(emb_node, Wn, bn, Wsn, bsn, We);

    dim3 grid(NN, BB);
    edge_mma_kernel<<<grid, 256, SMEM_SZ>>>(A, emb_edge, be, out, tmap, use_tma);
}